// round 1
// baseline (speedup 1.0000x reference)
#include <cuda_runtime.h>

// Problem constants
#define Bz 4
#define Sz 2048
#define Ez 2048
#define Hz 16
#define HDz 128
#define Mz (Bz*Sz)              // 8192
#define SCALE_F 0.08838834764831845f  // 1/sqrt(128)

// Scratch (device globals: allocation-free, graph-capturable)
__device__ __align__(16) float g_Q[(size_t)Bz*Hz*Sz*HDz];   // 64 MB, [B,H,S,HD]
__device__ __align__(16) float g_K[(size_t)Bz*Hz*Sz*HDz];
__device__ __align__(16) float g_V[(size_t)Bz*Hz*Sz*HDz];
__device__ __align__(16) float g_att[(size_t)Bz*Sz*Ez];     // [B,S,E]

typedef unsigned long long u64;

// ---- packed f32x2 helpers (FFMA2 path: 2x fp32 throughput on sm_103a) ----
__device__ __forceinline__ void fma2(u64 &d, u64 a, u64 b) {
    asm("fma.rn.f32x2 %0, %1, %2, %3;" : "=l"(d) : "l"(a), "l"(b), "l"(d));
}
__device__ __forceinline__ u64 mul2(u64 a, u64 b) {
    u64 d; asm("mul.rn.f32x2 %0, %1, %2;" : "=l"(d) : "l"(a), "l"(b)); return d;
}
__device__ __forceinline__ u64 pk2(float x, float y) {
    u64 r; asm("mov.b64 %0, {%1, %2};" : "=l"(r) : "f"(x), "f"(y)); return r;
}
__device__ __forceinline__ void unpk2(u64 v, float &x, float &y) {
    asm("mov.b64 {%0, %1}, %2;" : "=f"(x), "=f"(y) : "l"(v));
}

// ============================================================================
// SGEMM with bias: C = A @ W^T + bias.
// A: [M,K] row-major. W: [N,K] row-major (nn.Linear weight). bias: [N].
// HEADSPLIT=true writes C in [B,H,S,HD] layout (head-split for attention).
// 128x128 block tile, BK=8, 8x8 per thread, f32x2 packed accumulation,
// register prefetch of next K-tile to hide global-load latency.
// ============================================================================
template<bool HEADSPLIT>
__global__ void __launch_bounds__(256, 2) sgemm_bias(
    const float* __restrict__ A, const float* __restrict__ W,
    const float* __restrict__ bias, float* __restrict__ C,
    int K, int N)
{
    __shared__ __align__(16) float As[8][128];
    __shared__ __align__(16) float Bs[8][128];

    const int bm = blockIdx.y * 128;
    const int bn = blockIdx.x * 128;
    const int tid = threadIdx.x;
    const int tr = tid >> 4;          // 0..15 (row group)
    const int tc = tid & 15;          // 0..15 (col group)
    const int lr = tid >> 1;          // 0..127 load row
    const int lk = (tid & 1) << 2;    // 0 or 4

    const float* Aptr = A + (size_t)(bm + lr) * K + lk;
    const float* Wptr = W + (size_t)(bn + lr) * K + lk;

    u64 acc[8][4];
    #pragma unroll
    for (int i = 0; i < 8; i++)
        #pragma unroll
        for (int j = 0; j < 4; j++) acc[i][j] = 0ULL;

    float4 av = *(const float4*)(Aptr);
    float4 wv = *(const float4*)(Wptr);

    for (int k0 = 0; k0 < K; k0 += 8) {
        As[lk+0][lr] = av.x; As[lk+1][lr] = av.y; As[lk+2][lr] = av.z; As[lk+3][lr] = av.w;
        Bs[lk+0][lr] = wv.x; Bs[lk+1][lr] = wv.y; Bs[lk+2][lr] = wv.z; Bs[lk+3][lr] = wv.w;
        __syncthreads();

        if (k0 + 8 < K) {   // prefetch next tile while computing
            av = *(const float4*)(Aptr + k0 + 8);
            wv = *(const float4*)(Wptr + k0 + 8);
        }

        #pragma unroll
        for (int kk = 0; kk < 8; kk++) {
            float4 a0 = *(const float4*)&As[kk][tr*8];
            float4 a1 = *(const float4*)&As[kk][tr*8+4];
            float4 bb0 = *(const float4*)&Bs[kk][tc*8];
            float4 bb1 = *(const float4*)&Bs[kk][tc*8+4];
            u64 b2[4];
            b2[0] = pk2(bb0.x, bb0.y); b2[1] = pk2(bb0.z, bb0.w);
            b2[2] = pk2(bb1.x, bb1.y); b2[3] = pk2(bb1.z, bb1.w);
            float a[8] = {a0.x,a0.y,a0.z,a0.w,a1.x,a1.y,a1.z,a1.w};
            #pragma unroll
            for (int i = 0; i < 8; i++) {
                u64 ap = pk2(a[i], a[i]);
                fma2(acc[i][0], ap, b2[0]);
                fma2(acc[i][1], ap, b2[1]);
                fma2(acc[i][2], ap, b2[2]);
                fma2(acc[i][3], ap, b2[3]);
            }
        }
        __syncthreads();
    }

    // Epilogue
    const int n0 = bn + tc * 8;
    float4 bi0 = *(const float4*)&bias[n0];
    float4 bi1 = *(const float4*)&bias[n0+4];
    #pragma unroll
    for (int i = 0; i < 8; i++) {
        const int m = bm + tr * 8 + i;
        float r[8];
        unpk2(acc[i][0], r[0], r[1]);
        unpk2(acc[i][1], r[2], r[3]);
        unpk2(acc[i][2], r[4], r[5]);
        unpk2(acc[i][3], r[6], r[7]);
        r[0]+=bi0.x; r[1]+=bi0.y; r[2]+=bi0.z; r[3]+=bi0.w;
        r[4]+=bi1.x; r[5]+=bi1.y; r[6]+=bi1.z; r[7]+=bi1.w;
        float4 o0 = make_float4(r[0],r[1],r[2],r[3]);
        float4 o1 = make_float4(r[4],r[5],r[6],r[7]);
        size_t off;
        if (HEADSPLIT) {
            const int bb = m >> 11;        // /S
            const int ss = m & 2047;       // %S
            const int h0 = n0 >> 7;        // /HD
            const int d0 = n0 & 127;       // %HD
            off = (((size_t)(bb*Hz + h0))*Sz + ss)*HDz + d0;
        } else {
            off = (size_t)m * N + n0;
        }
        *(float4*)&C[off]   = o0;
        *(float4*)&C[off+4] = o1;
    }
}

// ============================================================================
// Fused attention (no mask): softmax(Q K^T * scale) V, per (b,h).
// BM=64 queries/block, BN=64 keys per tile, HD=128, 256 threads (16x16).
// Thread (tx,ty): score tile rows ty*4+i, cols j*16+tx; O tile rows ty*4+i,
// d-cols tx*8..tx*8+7. f32x2 packed over the d dimension. Online softmax.
// Writes output in [B,S,E] layout for the subsequent O-projection GEMM.
// ============================================================================
#define KPAD 132   // K tile row pad (reduces LDS bank conflicts on row-strided reads)

__global__ void __launch_bounds__(256) attn_kernel()
{
    extern __shared__ float sm[];
    float* Qs_ = sm;                      // [64][128]
    float* Ks_ = Qs_ + 64*128;            // [64][KPAD]
    float* Vs_ = Ks_ + 64*KPAD;           // [64][128]
    float* Ps_ = Vs_ + 64*128;            // [64][64]
#define QS(r,c) Qs_[(r)*128 + (c)]
#define KS(r,c) Ks_[(r)*KPAD + (c)]
#define VS(r,c) Vs_[(r)*128 + (c)]
#define PS(r,c) Ps_[(r)*64  + (c)]

    const int bh = blockIdx.y;            // 0..63
    const int qb = blockIdx.x * 64;
    const int b  = bh / Hz;
    const int h  = bh % Hz;
    const float* Qg = g_Q + (size_t)bh * Sz * HDz;
    const float* Kg = g_K + (size_t)bh * Sz * HDz;
    const float* Vg = g_V + (size_t)bh * Sz * HDz;

    const int tid = threadIdx.x;
    const int tx = tid & 15;
    const int ty = tid >> 4;
    const int ty4 = ty * 4;

    // Load Q tile (rows qb..qb+63)
    for (int idx = tid; idx < 64*32; idx += 256) {
        const int r = idx >> 5, c4 = (idx & 31) << 2;
        *(float4*)&QS(r, c4) = *(const float4*)&Qg[(size_t)(qb + r)*HDz + c4];
    }

    float mrow[4], lrow[4];
    u64 o2[4][4];
    #pragma unroll
    for (int i = 0; i < 4; i++) {
        mrow[i] = -1e30f; lrow[i] = 0.f;
        #pragma unroll
        for (int j = 0; j < 4; j++) o2[i][j] = 0ULL;
    }

    __syncthreads();

    for (int kt = 0; kt < Sz/64; kt++) {
        const int kbase = kt * 64;
        const float* Kt = Kg + (size_t)kbase * HDz;
        const float* Vt = Vg + (size_t)kbase * HDz;
        for (int idx = tid; idx < 64*32; idx += 256) {
            const int r = idx >> 5, c4 = (idx & 31) << 2;
            *(float4*)&KS(r, c4) = *(const float4*)&Kt[(size_t)r*HDz + c4];
            *(float4*)&VS(r, c4) = *(const float4*)&Vt[(size_t)r*HDz + c4];
        }
        __syncthreads();

        // --- scores: S = Q K^T, packed over d pairs ---
        u64 s2[4][4];
        #pragma unroll
        for (int i = 0; i < 4; i++)
            #pragma unroll
            for (int j = 0; j < 4; j++) s2[i][j] = 0ULL;

        #pragma unroll 4
        for (int d0 = 0; d0 < HDz; d0 += 4) {
            ulonglong2 qq[4], kk[4];
            #pragma unroll
            for (int i = 0; i < 4; i++) qq[i] = *(const ulonglong2*)&QS(ty4+i, d0);
            #pragma unroll
            for (int j = 0; j < 4; j++) kk[j] = *(const ulonglong2*)&KS(j*16+tx, d0);
            #pragma unroll
            for (int i = 0; i < 4; i++)
                #pragma unroll
                for (int j = 0; j < 4; j++) {
                    fma2(s2[i][j], qq[i].x, kk[j].x);
                    fma2(s2[i][j], qq[i].y, kk[j].y);
                }
        }

        float s[4][4];
        #pragma unroll
        for (int i = 0; i < 4; i++)
            #pragma unroll
            for (int j = 0; j < 4; j++) {
                float lo, hi; unpk2(s2[i][j], lo, hi);
                s[i][j] = (lo + hi) * SCALE_F;
            }

        // --- online softmax (row stats replicated across tx group) ---
        #pragma unroll
        for (int i = 0; i < 4; i++) {
            float rm = fmaxf(fmaxf(s[i][0], s[i][1]), fmaxf(s[i][2], s[i][3]));
            #pragma unroll
            for (int off = 8; off > 0; off >>= 1)
                rm = fmaxf(rm, __shfl_xor_sync(0xffffffffu, rm, off));
            const float mnew = fmaxf(mrow[i], rm);
            const float alpha = __expf(mrow[i] - mnew);
            mrow[i] = mnew;
            float rs = 0.f;
            #pragma unroll
            for (int j = 0; j < 4; j++) {
                const float p = __expf(s[i][j] - mnew);
                PS(ty4+i, j*16+tx) = p;
                rs += p;
            }
            #pragma unroll
            for (int off = 8; off > 0; off >>= 1)
                rs += __shfl_xor_sync(0xffffffffu, rs, off);
            lrow[i] = lrow[i] * alpha + rs;
            const u64 ap = pk2(alpha, alpha);
            #pragma unroll
            for (int j = 0; j < 4; j++) o2[i][j] = mul2(o2[i][j], ap);
        }
        __syncthreads();  // Ps visible to all

        // --- O += P V ---
        #pragma unroll 2
        for (int c = 0; c < 64; c++) {
            const ulonglong2 v0 = *(const ulonglong2*)&VS(c, tx*8);
            const ulonglong2 v1 = *(const ulonglong2*)&VS(c, tx*8 + 4);
            #pragma unroll
            for (int i = 0; i < 4; i++) {
                const float p = PS(ty4+i, c);
                const u64 ap = pk2(p, p);
                fma2(o2[i][0], ap, v0.x);
                fma2(o2[i][1], ap, v0.y);
                fma2(o2[i][2], ap, v1.x);
                fma2(o2[i][3], ap, v1.y);
            }
        }
        __syncthreads();  // before K/V tiles are overwritten
    }

    // --- normalize + write [B,S,E] ---
    #pragma unroll
    for (int i = 0; i < 4; i++) {
        const float inv = 1.0f / lrow[i];
        const int srow = qb + ty4 + i;
        float r[8];
        unpk2(o2[i][0], r[0], r[1]);
        unpk2(o2[i][1], r[2], r[3]);
        unpk2(o2[i][2], r[4], r[5]);
        unpk2(o2[i][3], r[6], r[7]);
        #pragma unroll
        for (int j = 0; j < 8; j++) r[j] *= inv;
        const size_t off = ((size_t)b*Sz + srow)*Ez + h*HDz + tx*8;
        *(float4*)&g_att[off]   = make_float4(r[0],r[1],r[2],r[3]);
        *(float4*)&g_att[off+4] = make_float4(r[4],r[5],r[6],r[7]);
    }
}

#define ATTN_SMEM ((64*128 + 64*KPAD + 64*128 + 64*64) * (int)sizeof(float))

// ============================================================================
extern "C" void kernel_launch(void* const* d_in, const int* in_sizes, int n_in,
                              void* d_out, int out_size)
{
    const float* QKV = (const float*)d_in[0];
    const float* Wq  = (const float*)d_in[1];
    const float* bq  = (const float*)d_in[2];
    const float* Wk  = (const float*)d_in[3];
    const float* bk  = (const float*)d_in[4];
    const float* Wv  = (const float*)d_in[5];
    const float* bv  = (const float*)d_in[6];
    const float* Wo  = (const float*)d_in[7];
    const float* bo  = (const float*)d_in[8];
    // d_in[9] = is_causal: reference masking is a no-op; ignored.
    float* out = (float*)d_out;

    void *pQ, *pK, *pV, *pAtt;
    cudaGetSymbolAddress(&pQ, g_Q);
    cudaGetSymbolAddress(&pK, g_K);
    cudaGetSymbolAddress(&pV, g_V);
    cudaGetSymbolAddress(&pAtt, g_att);

    cudaFuncSetAttribute(attn_kernel,
                         cudaFuncAttributeMaxDynamicSharedMemorySize, ATTN_SMEM);

    const dim3 ggrid(Ez/128, Mz/128);   // (16, 64)
    const dim3 gblk(256);

    // Q/K/V projections -> head-split [B,H,S,HD]
    sgemm_bias<true><<<ggrid, gblk>>>(QKV, Wq, bq, (float*)pQ, Ez, Ez);
    sgemm_bias<true><<<ggrid, gblk>>>(QKV, Wk, bk, (float*)pK, Ez, Ez);
    sgemm_bias<true><<<ggrid, gblk>>>(QKV, Wv, bv, (float*)pV, Ez, Ez);

    // Fused attention -> g_att [B,S,E]
    attn_kernel<<<dim3(Sz/64, Bz*Hz), gblk, ATTN_SMEM>>>();

    // Output projection -> d_out [B,S,E]
    sgemm_bias<false><<<ggrid, gblk>>>((const float*)pAtt, Wo, bo, out, Ez, Ez);
}